// round 1
// baseline (speedup 1.0000x reference)
#include <cuda_runtime.h>

// CumulantSOAP_CV: per-column mean & variance over X (200000 x 576 fp32),
// then project (cum - mu) @ W  -> (1 x 4).
// Single streaming pass (sum, sumsq), HBM-bound.

#define N_ROWS   200000
#define P        576
#define NBLK     296
#define RPB      ((N_ROWS + NBLK - 1) / NBLK)   // 676 rows per block
#define NPART    (NBLK * 4)                     // 1184 sub-partials (4 row-phases per block)

// Scratch (allocation-free: __device__ globals). 2 x 2.6 MB -> L2-resident.
__device__ float g_ps[NPART][P];   // partial sums
__device__ float g_pq[NPART][P];   // partial sums of squares
__device__ float g_colsum[P];
__device__ float g_colsq[P];

// ---------------------------------------------------------------------------
// Pass 1: streaming reduction over X. blockDim = 576.
//   thread t -> column group c4 = t % 144 (4 columns via float4),
//               row phase   rs = t / 144 (0..3)
// Coalescing: within a warp, consecutive threads load consecutive float4s.
// ---------------------------------------------------------------------------
__global__ __launch_bounds__(576) void pass1_kernel(const float* __restrict__ X) {
    const int b  = blockIdx.x;
    const int t  = threadIdx.x;
    const int c4 = t % 144;      // float4 column index (0..143)
    const int rs = t / 144;      // 0..3

    const int r0 = b * RPB;
    int r1 = r0 + RPB;
    if (r1 > N_ROWS) r1 = N_ROWS;

    const float4* __restrict__ Xv = reinterpret_cast<const float4*>(X);

    float4 s = make_float4(0.f, 0.f, 0.f, 0.f);
    float4 q = make_float4(0.f, 0.f, 0.f, 0.f);

    #pragma unroll 4
    for (int r = r0 + rs; r < r1; r += 4) {
        float4 x = Xv[(size_t)r * 144 + c4];
        s.x += x.x; s.y += x.y; s.z += x.z; s.w += x.w;
        q.x += x.x * x.x; q.y += x.y * x.y; q.z += x.z * x.z; q.w += x.w * x.w;
    }

    const int p = b * 4 + rs;
    reinterpret_cast<float4*>(&g_ps[p][0])[c4] = s;
    reinterpret_cast<float4*>(&g_pq[p][0])[c4] = q;
}

// ---------------------------------------------------------------------------
// Pass 2: reduce the 1184 partials for each column. One block per column,
// 128 threads, deterministic shared-memory tree. Data is L2-resident.
// ---------------------------------------------------------------------------
__global__ __launch_bounds__(128) void pass2_kernel() {
    const int c = blockIdx.x;    // column 0..575
    const int t = threadIdx.x;   // 0..127

    float s = 0.f, q = 0.f;
    for (int i = t; i < NPART; i += 128) {
        s += g_ps[i][c];
        q += g_pq[i][c];
    }

    __shared__ float ss[128];
    __shared__ float sq[128];
    ss[t] = s; sq[t] = q;
    __syncthreads();

    #pragma unroll
    for (int w = 64; w > 0; w >>= 1) {
        if (t < w) { ss[t] += ss[t + w]; sq[t] += sq[t + w]; }
        __syncthreads();
    }
    if (t == 0) { g_colsum[c] = ss[0]; g_colsq[c] = sq[0]; }
}

// ---------------------------------------------------------------------------
// Pass 3: cumulants, subtract mu, project by W (1728 x 4), reduce to out[4].
// One block, 576 threads (thread c owns column c -> cumulant rows 3c..3c+2).
// mom1 = mean(X - m) == 0 analytically (reference's fp32 residual ~1e-7 is
// negligible at the 1e-3 output tolerance).
// ---------------------------------------------------------------------------
__global__ __launch_bounds__(576) void pass3_kernel(const float* __restrict__ mu,
                                                    const float* __restrict__ W,
                                                    float* __restrict__ out) {
    const int c = threadIdx.x;   // 0..575
    const float invN = 1.0f / (float)N_ROWS;

    const float m    = g_colsum[c] * invN;
    const float mom2 = g_colsq[c] * invN - m * m;

    const int j0 = 3 * c;
    const float d0 = m    - mu[j0 + 0];
    const float d1 = 0.f  - mu[j0 + 1];
    const float d2 = mom2 - mu[j0 + 2];

    float4 acc;
    acc.x = d0 * W[(j0 + 0) * 4 + 0] + d1 * W[(j0 + 1) * 4 + 0] + d2 * W[(j0 + 2) * 4 + 0];
    acc.y = d0 * W[(j0 + 0) * 4 + 1] + d1 * W[(j0 + 1) * 4 + 1] + d2 * W[(j0 + 2) * 4 + 1];
    acc.z = d0 * W[(j0 + 0) * 4 + 2] + d1 * W[(j0 + 1) * 4 + 2] + d2 * W[(j0 + 2) * 4 + 2];
    acc.w = d0 * W[(j0 + 0) * 4 + 3] + d1 * W[(j0 + 1) * 4 + 3] + d2 * W[(j0 + 2) * 4 + 3];

    __shared__ float4 sh[576];
    sh[c] = acc;
    __syncthreads();

    // 576 -> 64 (deterministic fixed-stride gather), then 64 -> 1 tree.
    if (c < 64) {
        float4 a = sh[c];
        for (int i = c + 64; i < 576; i += 64) {
            float4 b = sh[i];
            a.x += b.x; a.y += b.y; a.z += b.z; a.w += b.w;
        }
        sh[c] = a;
    }
    __syncthreads();
    #pragma unroll
    for (int w = 32; w > 0; w >>= 1) {
        if (c < w) {
            float4 a = sh[c], b = sh[c + w];
            a.x += b.x; a.y += b.y; a.z += b.z; a.w += b.w;
            sh[c] = a;
        }
        __syncthreads();
    }

    if (c == 0) {
        out[0] = sh[0].x;
        out[1] = sh[0].y;
        out[2] = sh[0].z;
        out[3] = sh[0].w;
    }
}

extern "C" void kernel_launch(void* const* d_in, const int* in_sizes, int n_in,
                              void* d_out, int out_size) {
    (void)in_sizes; (void)n_in; (void)out_size;
    const float* X  = (const float*)d_in[0];   // (200000, 576)
    const float* mu = (const float*)d_in[1];   // (1728,)
    const float* W  = (const float*)d_in[2];   // (1728, 4)
    float* out = (float*)d_out;                // (1, 4)

    pass1_kernel<<<NBLK, 576>>>(X);
    pass2_kernel<<<P, 128>>>();
    pass3_kernel<<<1, 576>>>(mu, W, out);
}